// round 6
// baseline (speedup 1.0000x reference)
#include <cuda_runtime.h>
#include <cstdint>
#include <cub/device/device_radix_sort.cuh>

#define BN 4
#define GN 25
#define AN 147456          // 128*128*9
#define TOTN 147456
#define NUMPOS 73728
#define CAP 131072         // pos capacity per batch (pow2)
#define NBLK 576           // AN / 256
#define NKEY (BN * CAP)    // 524288

#define FMW 128.0f
#define MIN_POS 0.15f
#define POS_TH 0.7f
#define NEG_TH 0.3f

// ------------------ static device scratch (no allocs allowed) ------------------
__device__ unsigned long long g_state[BN][NBLK];  // lookback: flag<<62|pos<<22|neg
__device__ unsigned int  g_tileCtr[BN];
__device__ int           g_posCount[BN];
__device__ unsigned int  g_keysIn[NKEY];
__device__ unsigned int  g_valsIn[NKEY];
__device__ unsigned int  g_keysOut[NKEY];
__device__ unsigned int  g_valsOut[NKEY];
__device__ unsigned char g_sortTemp[24 << 20];
__device__ unsigned int  g_negbuf[BN][TOTN];

// ------------------ reset + pad-fill keys (graph-replay determinism) ----------
__global__ void k_zero() {
    int t = blockIdx.x * blockDim.x + threadIdx.x;
    int n = gridDim.x * blockDim.x;
    for (int i = t; i < NKEY; i += n)
        g_keysIn[i] = ((unsigned)(i / CAP)) << 30;   // iou=0 pad, sinks in batch
    unsigned long long* st = &g_state[0][0];
    for (int i = t; i < BN * NBLK; i += n) st[i] = 0ull;
    if (t < BN) g_tileCtr[t] = 0u;
}

// ------------------ IoU helper ------------------------------------------------
__device__ __forceinline__ float iou_one(float ax1, float ay1, float ax2, float ay2,
                                         float areaA,
                                         const float* sg, float sarea) {
    float ltx = fmaxf(ax1, sg[0]);
    float lty = fmaxf(ay1, sg[1]);
    float rbx = fminf(ax2, sg[2]);
    float rby = fminf(ay2, sg[3]);
    float wx = fmaxf(__fsub_rn(rbx, ltx), 0.0f);
    float wy = fmaxf(__fsub_rn(rby, lty), 0.0f);
    float inter = __fmul_rn(wx, wy);
    float v = 0.0f;
    if (inter > 0.0f) {
        float uni = __fsub_rn(__fadd_rn(areaA, sarea), inter);
        v = __fdiv_rn(inter, uni);
    }
    return v;
}

__device__ __forceinline__ unsigned long long pack_state(unsigned long long flag,
                                                         unsigned long long pos,
                                                         unsigned long long neg) {
    return (flag << 62) | (pos << 22) | neg;
}

// ------------------ fused assign + chained-scan + scatter ---------------------
// grid (NBLK, BN), 256 threads. One pass: IoU -> masks -> decoupled-lookback
// offsets -> direct key/val + neg writes. Deterministic: offsets depend only on
// tile index.
__global__ void __launch_bounds__(256) k_fused(const float* __restrict__ anchors,
                                               const float* __restrict__ gtb) {
    __shared__ float s_g[GN][4];
    __shared__ float s_area[GN];
    __shared__ int s_w[8];
    __shared__ int s_tile, s_posOff, s_negOff;
    __shared__ unsigned s_stage[GN * 256];

    int t = threadIdx.x;
    int b = blockIdx.y;

    if (t == 0) s_tile = (int)atomicAdd(&g_tileCtr[b], 1u);
    if (t < GN) {
        float x1 = __fmul_rn(gtb[(b * GN + t) * 4 + 0], 0.125f);
        float y1 = __fmul_rn(gtb[(b * GN + t) * 4 + 1], 0.125f);
        float x2 = __fmul_rn(gtb[(b * GN + t) * 4 + 2], 0.125f);
        float y2 = __fmul_rn(gtb[(b * GN + t) * 4 + 3], 0.125f);
        s_g[t][0] = x1; s_g[t][1] = y1; s_g[t][2] = x2; s_g[t][3] = y2;
        s_area[t] = __fmul_rn(__fsub_rn(x2, x1), __fsub_rn(y2, y1));
    }
    __syncthreads();
    int tile = s_tile;
    int a = tile * 256 + t;

    // ---- IoU + classification (iou stays in registers) ----
    const float4 av = *reinterpret_cast<const float4*>(
        anchors + (((long long)b * AN + a) << 2));
    float ax1 = av.x, ay1 = av.y, ax2 = av.z, ay2 = av.w;
    bool valid = (ax1 >= 0.0f) && (ay1 >= 0.0f) && (ax2 <= FMW) && (ay2 <= FMW);
    float areaA = __fmul_rn(__fsub_rn(ax2, ax1), __fsub_rn(ay2, ay1));

    float iou[GN];
    float rmax = 0.0f;
    #pragma unroll
    for (int g = 0; g < GN; g++) {
        float v = iou_one(ax1, ay1, ax2, ay2, areaA, s_g[g], s_area[g]);
        iou[g] = v;
        rmax = fmaxf(rmax, v);
    }
    unsigned pm = 0, nm = 0;
    #pragma unroll
    for (int g = 0; g < GN; g++) {
        float v = iou[g];
        bool pos = valid && (((v == rmax) && (v > MIN_POS)) || (v >= POS_TH));
        bool neg = valid && (v < NEG_TH) && !pos;
        if (pos) pm |= (1u << g);
        if (neg) nm |= (1u << g);
    }

    // ---- intra-block packed scan: (pos<<16)|neg (tile totals <= 6400) ----
    int packed = (__popc(pm) << 16) | __popc(nm);
    int lane = t & 31, warp = t >> 5;
    int v = packed;
    #pragma unroll
    for (int o = 1; o < 32; o <<= 1) {
        int u = __shfl_up_sync(~0u, v, o);
        if (lane >= o) v += u;
    }
    if (lane == 31) s_w[warp] = v;
    __syncthreads();
    if (warp == 0 && lane < 8) {
        int w = s_w[lane];
        #pragma unroll
        for (int o = 1; o < 8; o <<= 1) {
            int u = __shfl_up_sync(0xff, w, o);
            if (lane >= o) w += u;
        }
        s_w[lane] = w;
    }
    __syncthreads();
    int total = s_w[7];
    int excl = (v - packed) + (warp ? s_w[warp - 1] : 0);
    int posExcl = excl >> 16;
    int negExcl = excl & 0xFFFF;
    unsigned long long posA = (unsigned long long)(total >> 16);
    unsigned long long negA = (unsigned long long)(total & 0xFFFF);

    // ---- decoupled lookback (thread 0) ----
    if (t == 0) {
        if (tile == 0) {
            atomicExch(&g_state[b][0], pack_state(2ull, posA, negA));
            s_posOff = 0; s_negOff = 0;
            if (tile == NBLK - 1) g_posCount[b] = (int)posA;
        } else {
            atomicExch(&g_state[b][tile], pack_state(1ull, posA, negA));
            unsigned long long posE = 0, negE = 0;
            int p = tile - 1;
            while (true) {
                unsigned long long s =
                    *((volatile unsigned long long*)&g_state[b][p]);
                unsigned long long f = s >> 62;
                if (f == 0ull) continue;
                posE += (s >> 22) & 0x3FFFFFull;
                negE += s & 0x3FFFFFull;
                if (f == 2ull) break;
                p--;
            }
            atomicExch(&g_state[b][tile],
                       pack_state(2ull, posE + posA, negE + negA));
            s_posOff = (int)posE;
            s_negOff = (int)negE;
            if (tile == NBLK - 1) g_posCount[b] = (int)(posE + posA);
        }
    }
    __syncthreads();
    int posOff = s_posOff;
    int negOff = s_negOff;

    // ---- positives: write key/val at exact global rank ----
    if (pm) {
        int r = posOff + posExcl;
        unsigned mm = pm;
        while (mm) {
            int g = __ffs(mm) - 1;
            mm &= mm - 1;
            if (r < CAP) {
                g_keysIn[b * CAP + r] = ((unsigned)b << 30) | __float_as_uint(iou[g]);
                g_valsIn[b * CAP + r] = (unsigned)(a * GN + g);
            }
            r++;
        }
    }

    // ---- negatives: smem stage then coalesced copy ----
    if (negOff < TOTN) {
        int r = negExcl;
        unsigned mm = nm;
        unsigned base = (unsigned)(a * GN);
        while (mm) {
            int g = __ffs(mm) - 1;
            mm &= mm - 1;
            s_stage[r++] = base + (unsigned)g;
        }
        __syncthreads();
        int lim = min((int)negA, TOTN - negOff);
        for (int i = t; i < lim; i += 256)
            g_negbuf[b][negOff + i] = s_stage[i];
    }
}

// ------------------ final gather + offsets + output ---------------------------
__global__ void k_output(const float* __restrict__ anchors,
                         const float* __restrict__ gtb,
                         const int* __restrict__ cls,
                         float* __restrict__ out) {
    __shared__ float s_gx1[GN], s_gy1[GN], s_gx2[GN], s_gy2[GN];
    __shared__ float s_cls[GN];

    int t = blockIdx.x * blockDim.x + threadIdx.x;
    int b = t / TOTN;
    if (b >= BN) return;
    int j = t % TOTN;

    if (threadIdx.x < GN) {
        const float* gp = gtb + (b * GN + threadIdx.x) * 4;
        s_gx1[threadIdx.x] = gp[0] * 0.125f;
        s_gy1[threadIdx.x] = gp[1] * 0.125f;
        s_gx2[threadIdx.x] = gp[2] * 0.125f;
        s_gy2[threadIdx.x] = gp[3] * 0.125f;
        s_cls[threadIdx.x] = (float)cls[b * GN + threadIdx.x];
    }
    __syncthreads();

    int P = g_posCount[b];
    int m = min(P, NUMPOS);

    unsigned flat;
    float obj;
    if (j < m) {
        // descending sort => batch b occupies block (BN-1-b)*CAP
        flat = g_valsOut[(BN - 1 - b) * CAP + j];
        obj = 1.0f;
    } else {
        flat = g_negbuf[b][j - m];
        obj = 0.0f;
    }

    int ai = (int)(flat / GN);
    int gi = (int)(flat % GN);

    const float4 av = *reinterpret_cast<const float4*>(
        anchors + (((long long)b * AN + ai) << 2));
    float ax1 = av.x, ay1 = av.y, ax2 = av.z, ay2 = av.w;

    float gx1 = s_gx1[gi], gy1 = s_gy1[gi];
    float gx2 = s_gx2[gi], gy2 = s_gy2[gi];

    float acx = (ax1 + ax2) * 0.5f, acy = (ay1 + ay2) * 0.5f;
    float aw = ax2 - ax1, ah = ay2 - ay1;
    float gcx = (gx1 + gx2) * 0.5f, gcy = (gy1 + gy2) * 0.5f;
    float gw = gx2 - gx1, gh = gy2 - gy1;

    float tx = (gcx - acx) / aw;
    float ty = (gcy - acy) / ah;
    float tw = logf(gw / aw);
    float th = logf(gh / ah);

    long long r = (long long)b * TOTN + j;
    const long long O_OBJ = (long long)BN * TOTN * 4;
    const long long O_CLS = O_OBJ + (long long)BN * TOTN;
    const long long O_OFF = O_CLS + (long long)BN * TOTN;

    *reinterpret_cast<float4*>(out + r * 4) = make_float4(ax1, ay1, ax2, ay2);
    out[O_OBJ + r] = obj;
    out[O_CLS + r] = s_cls[gi];
    *reinterpret_cast<float4*>(out + O_OFF + r * 4) = make_float4(tx, ty, tw, th);
}

// ------------------------------------------------------------------------------
extern "C" void kernel_launch(void* const* d_in, const int* in_sizes, int n_in,
                              void* d_out, int out_size) {
    const float* anchors = (const float*)d_in[0];
    const float* gtb     = (const float*)d_in[1];
    const int*   cls     = (const int*)d_in[2];
    float*       out     = (float*)d_out;

    void *d_ki, *d_ko, *d_vi, *d_vo, *d_temp;
    cudaGetSymbolAddress(&d_ki, g_keysIn);
    cudaGetSymbolAddress(&d_ko, g_keysOut);
    cudaGetSymbolAddress(&d_vi, g_valsIn);
    cudaGetSymbolAddress(&d_vo, g_valsOut);
    cudaGetSymbolAddress(&d_temp, g_sortTemp);

    size_t temp_bytes = 0;
    cub::DeviceRadixSort::SortPairsDescending(
        nullptr, temp_bytes,
        (const unsigned*)d_ki, (unsigned*)d_ko,
        (const unsigned*)d_vi, (unsigned*)d_vo,
        NKEY, 0, 32);
    if (temp_bytes > (24u << 20)) temp_bytes = (24u << 20);

    k_zero<<<512, 256>>>();
    k_fused<<<dim3(NBLK, BN), 256>>>(anchors, gtb);

    cub::DeviceRadixSort::SortPairsDescending(
        d_temp, temp_bytes,
        (const unsigned*)d_ki, (unsigned*)d_ko,
        (const unsigned*)d_vi, (unsigned*)d_vo,
        NKEY, 0, 32);

    k_output<<<(BN * TOTN + 255) / 256, 256>>>(anchors, gtb, cls, out);
}